// round 9
// baseline (speedup 1.0000x reference)
#include <cuda_runtime.h>

// PureCascadedBitFFN: out[elem, j] = j-th bit (LSB=0) of
// k = ceil(distance[elem] - 0.5) (exact reduction of the 16-step sigmoid
// cascade in the reference).
//
// 128 MB f32 output, never re-read: pinned at the GB300 HBM write wall.
// Steady-state 23.0us = 5.9 TB/s total DRAM traffic (~74% of 8 TB/s spec);
// LSU/ALU/LTS all have headroom. Verified neutral/worse across rounds:
// smem read-dedup, persistent grid, write-through (regressed), I2F->int-
// select, 256-thread vs 512-thread blocks. TMA would hit the same
// path-independent LTS cap.
//
// Final config: 512-thread blocks, 8192-quad tiles (32 KB contiguous write
// extent per block for HBM row-buffer locality), 16 quads/thread as 16
// coalesced 2KB block-wide STG.128 bursts, __stcs evict-first, bits
// materialized by integer select of 0x3F800000.

__global__ __launch_bounds__(512) void cascaded_bits_kernel(
    const float* __restrict__ dist,
    float4* __restrict__ out)
{
    const int base = blockIdx.x * 8192 + threadIdx.x;

    float r[16];
    #pragma unroll
    for (int i = 0; i < 16; i++)
        r[i] = __ldg(&dist[(base + i * 512) >> 2]);

    int k[16];
    #pragma unroll
    for (int i = 0; i < 16; i++)
        k[i] = __float2int_ru(r[i] - 0.5f);   // exact round-half-down

    #pragma unroll
    for (int i = 0; i < 16; i++) {
        const int q   = base + i * 512;
        const int bit = (q & 3) << 2;         // starting bit: 0,4,8,12
        float4 v;
        v.x = __int_as_float(((k[i] >> (bit + 0)) & 1) * 0x3F800000);
        v.y = __int_as_float(((k[i] >> (bit + 1)) & 1) * 0x3F800000);
        v.z = __int_as_float(((k[i] >> (bit + 2)) & 1) * 0x3F800000);
        v.w = __int_as_float(((k[i] >> (bit + 3)) & 1) * 0x3F800000);
        __stcs(&out[q], v);                   // streaming: evict-first in L2
    }
}

extern "C" void kernel_launch(void* const* d_in, const int* in_sizes, int n_in,
                              void* d_out, int out_size)
{
    const float* dist = (const float*)d_in[0];
    float4* out = (float4*)d_out;

    int n_elems = in_sizes[0];            // 512*4096 = 2,097,152
    int nquads  = n_elems * 4;            // 8,388,608
    int blocks  = nquads / 8192;          // 1024 (exact)

    cascaded_bits_kernel<<<blocks, 512>>>(dist, out);
}

// round 10
// speedup vs baseline: 1.0694x; 1.0694x over previous
#include <cuda_runtime.h>

// PureCascadedBitFFN: out[elem, j] = j-th bit (LSB=0) of
// k = ceil(distance[elem] - 0.5) (exact reduction of the 16-step sigmoid
// cascade in the reference).
//
// 128 MB f32 output, never re-read: pinned at the GB300 HBM write wall.
// Steady-state 23.0us = 5.9 TB/s total DRAM traffic (~74% of 8 TB/s spec);
// LSU/ALU/LTS all have headroom, so this is the floor. Verified
// neutral/worse across the session: smem read-dedup (R4), persistent grid
// (R5, +2us), write-through (R6, +4us), I2F->int-select (R7, neutral),
// 16 quads/thread at grid=1024 (R9, +1.6us from occupancy loss). TMA would
// hit the same path-independent LTS cap.
//
// FINAL best-known config (R8: bench 23.04us, kernel 22.37us):
// 512-thread blocks, 4096-quad tiles, grid=2048. Each thread: 8 quads
// strided by 512 -> 8 coalesced 2KB block-wide STG.128 bursts; front-batched
// __ldg reads; __stcs evict-first (L2 buffers + burst-forms the DRAM drain);
// bits materialized by integer select of 0x3F800000 (no convert pipe).

__global__ __launch_bounds__(512) void cascaded_bits_kernel(
    const float* __restrict__ dist,
    float4* __restrict__ out)
{
    const int base = blockIdx.x * 4096 + threadIdx.x;

    float r[8];
    #pragma unroll
    for (int i = 0; i < 8; i++)
        r[i] = __ldg(&dist[(base + i * 512) >> 2]);

    int k[8];
    #pragma unroll
    for (int i = 0; i < 8; i++)
        k[i] = __float2int_ru(r[i] - 0.5f);   // exact round-half-down

    #pragma unroll
    for (int i = 0; i < 8; i++) {
        const int q   = base + i * 512;
        const int bit = (q & 3) << 2;         // starting bit: 0,4,8,12
        float4 v;
        v.x = __int_as_float(((k[i] >> (bit + 0)) & 1) * 0x3F800000);
        v.y = __int_as_float(((k[i] >> (bit + 1)) & 1) * 0x3F800000);
        v.z = __int_as_float(((k[i] >> (bit + 2)) & 1) * 0x3F800000);
        v.w = __int_as_float(((k[i] >> (bit + 3)) & 1) * 0x3F800000);
        __stcs(&out[q], v);                   // streaming: evict-first in L2
    }
}

extern "C" void kernel_launch(void* const* d_in, const int* in_sizes, int n_in,
                              void* d_out, int out_size)
{
    const float* dist = (const float*)d_in[0];
    float4* out = (float4*)d_out;

    int n_elems = in_sizes[0];            // 512*4096 = 2,097,152
    int nquads  = n_elems * 4;            // 8,388,608
    int blocks  = nquads / 4096;          // 2048 (exact)

    cascaded_bits_kernel<<<blocks, 512>>>(dist, out);
}